// round 3
// baseline (speedup 1.0000x reference)
#include <cuda_runtime.h>
#include <cuda_fp16.h>
#include <cstdint>

// ============================================================================
// y[4096,12288] = x[4096,3072] @ dequant(w_q,scales)^T + bias
//
// Toolchain targets base sm_100 (no 'a' suffix) => tcgen05 unavailable.
// Path: pre-pass dequant to fp16 scratch, then mma.sync.m16n8k16 (HMMA) GEMM
// with cp.async 3-stage pipeline and ldmatrix fragment loads.
// ============================================================================

#define M_TOK 4096
#define N_OUT 12288
#define K_IN  3072

// Scratch (__device__ globals = sanctioned allocation-free scratch)
__device__ __half g_xh[(size_t)M_TOK * K_IN];   // 25 MB
__device__ __half g_wh[(size_t)N_OUT * K_IN];   // 75.5 MB

// ---------------- tile config ----------------
constexpr int BM = 128;
constexpr int BN = 128;
constexpr int BK = 64;            // fp16 K per stage = 128B rows (SW128 atom)
constexpr int STAGES = 3;
constexpr int KT = K_IN / BK;     // 48

constexpr uint32_t A_STAGE_BYTES = BM * BK * 2;                   // 16384
constexpr uint32_t B_STAGE_BYTES = BN * BK * 2;                   // 16384
constexpr uint32_t STAGE_BYTES   = A_STAGE_BYTES + B_STAGE_BYTES; // 32768
constexpr uint32_t SMEM_SIZE     = 1024 + STAGES * STAGE_BYTES;   // 99328

// ---------------- PTX helpers ----------------
__device__ __forceinline__ uint32_t smem_u32(const void* p) {
    uint32_t a;
    asm("{ .reg .u64 t; cvta.to.shared.u64 t, %1; cvt.u32.u64 %0, t; }"
        : "=r"(a) : "l"(p));
    return a;
}

__device__ __forceinline__ void cp_async16(uint32_t smem_dst, const void* gsrc) {
    asm volatile("cp.async.cg.shared.global [%0], [%1], 16;"
                 :: "r"(smem_dst), "l"(__cvta_generic_to_global(gsrc)) : "memory");
}

__device__ __forceinline__ void cp_commit() {
    asm volatile("cp.async.commit_group;" ::: "memory");
}

__device__ __forceinline__ void cp_wait1() {
    asm volatile("cp.async.wait_group 1;" ::: "memory");
}

__device__ __forceinline__ void ldsm_x4(uint32_t& r0, uint32_t& r1,
                                        uint32_t& r2, uint32_t& r3,
                                        uint32_t addr) {
    asm volatile("ldmatrix.sync.aligned.m8n8.x4.shared.b16 {%0,%1,%2,%3}, [%4];"
                 : "=r"(r0), "=r"(r1), "=r"(r2), "=r"(r3) : "r"(addr));
}

__device__ __forceinline__ void mma16816(float* c, const uint32_t* a,
                                         const uint32_t* b) {
    asm volatile(
        "mma.sync.aligned.m16n8k16.row.col.f32.f16.f16.f32 "
        "{%0,%1,%2,%3}, {%4,%5,%6,%7}, {%8,%9}, {%0,%1,%2,%3};"
        : "+f"(c[0]), "+f"(c[1]), "+f"(c[2]), "+f"(c[3])
        : "r"(a[0]), "r"(a[1]), "r"(a[2]), "r"(a[3]), "r"(b[0]), "r"(b[1]));
}

__device__ __forceinline__ uint32_t pack_h2(float a, float b) {
    __half2 h = __floats2half2_rn(a, b);
    return *reinterpret_cast<uint32_t*>(&h);
}

// ============================================================================
// Pre-pass 1: x (f32) -> g_xh (fp16), 8 elem/thread
// ============================================================================
__global__ void DequantingLinear_convert_x(const float* __restrict__ x) {
    size_t t = (size_t)blockIdx.x * blockDim.x + threadIdx.x;
    const size_t total = (size_t)M_TOK * K_IN / 8;
    if (t >= total) return;
    const float4* p = reinterpret_cast<const float4*>(x) + t * 2;
    float4 a = p[0], b = p[1];
    uint4 o;
    o.x = pack_h2(a.x, a.y);
    o.y = pack_h2(a.z, a.w);
    o.z = pack_h2(b.x, b.y);
    o.w = pack_h2(b.z, b.w);
    reinterpret_cast<uint4*>(g_xh)[t] = o;
}

// ============================================================================
// Pre-pass 2: W = q*scale -> g_wh (fp16), 8 elem/thread (never straddles block)
// ============================================================================
__global__ void DequantingLinear_dequant_w(const int* __restrict__ q,
                                           const float* __restrict__ sc) {
    size_t t = (size_t)blockIdx.x * blockDim.x + threadIdx.x;
    const size_t total = (size_t)N_OUT * K_IN / 8;
    if (t >= total) return;
    size_t o = t / (K_IN / 8);
    int gk = (int)(t % (K_IN / 8));
    int k0 = gk * 8;
    float s = sc[o * (K_IN / 32) + (k0 >> 5)];
    const int4* p = reinterpret_cast<const int4*>(q + o * (size_t)K_IN + k0);
    int4 a = p[0], b = p[1];
    uint4 r;
    r.x = pack_h2((float)a.x * s, (float)a.y * s);
    r.y = pack_h2((float)a.z * s, (float)a.w * s);
    r.z = pack_h2((float)b.x * s, (float)b.y * s);
    r.w = pack_h2((float)b.z * s, (float)b.w * s);
    reinterpret_cast<uint4*>(g_wh)[t] = r;
}

// ============================================================================
// Main GEMM: 128x128x64 tile, 8 warps (warp grid 4M x 2N, warp tile 32x64),
// mma.sync m16n8k16 fp16->fp32, 3-stage cp.async pipeline, SW128 swizzle.
// ============================================================================
__global__ void __launch_bounds__(256)
DequantingLinear_gemm_hmma(const float* __restrict__ bias,
                           float* __restrict__ out) {
    extern __shared__ char smem_raw[];
    uint32_t base = (smem_u32(smem_raw) + 1023u) & ~1023u;
    uint32_t stage0 = base;

    const int tid  = threadIdx.x;
    const int wid  = tid >> 5;
    const int lane = tid & 31;
    const int warp_m = wid & 3;   // 0..3 -> M offset warp_m*32
    const int warp_n = wid >> 2;  // 0..1 -> N offset warp_n*64
    const int m0 = blockIdx.y * BM;
    const int n0 = blockIdx.x * BN;

    const __half* Ag = g_xh + (size_t)m0 * K_IN;
    const __half* Bg = g_wh + (size_t)n0 * K_IN;

    // ---- producer: stage = 128 rows x 128B = 1024 x 16B chunks per operand,
    // 8 chunks per 128B row => r = idx>>3, cc = idx&7. 4 chunks/thread each.
    auto load_stage = [&](int s, int kt) {
        uint32_t a_s = stage0 + s * STAGE_BYTES;
        uint32_t b_s = a_s + A_STAGE_BYTES;
        int koff = kt * BK;
        #pragma unroll
        for (int c = 0; c < 4; c++) {
            int idx = tid + c * 256;            // 0..1023
            int r = idx >> 3, cc = idx & 7;     // 128 rows x 8 chunks
            uint32_t off = (uint32_t)(r * 128 + cc * 16);
            uint32_t swz = off ^ ((off >> 3) & 0x70);
            cp_async16(a_s + swz, Ag + (size_t)r * K_IN + koff + cc * 8);
        }
        #pragma unroll
        for (int c = 0; c < 4; c++) {
            int idx = tid + c * 256;
            int r = idx >> 3, cc = idx & 7;
            uint32_t off = (uint32_t)(r * 128 + cc * 16);
            uint32_t swz = off ^ ((off >> 3) & 0x70);
            cp_async16(b_s + swz, Bg + (size_t)r * K_IN + koff + cc * 8);
        }
        cp_commit();
    };

    // ---- per-lane ldmatrix address components (swizzle key = (row&7)<<4) ----
    // A: row = warp_m*32 + mi*16 + (lane&15), k-seg = (lane>>4)*16 bytes
    uint32_t a_rowbase[2], a_key[2];
    #pragma unroll
    for (int mi = 0; mi < 2; mi++) {
        int row = warp_m * 32 + mi * 16 + (lane & 15);
        a_rowbase[mi] = (uint32_t)row * 128;
        a_key[mi] = (uint32_t)((row & 7) << 4);
    }
    uint32_t a_seg = (uint32_t)((lane >> 4) * 16);
    // B: nrow = warp_n*64 + nb*16 + (lane&7) + ((lane>>4)<<3), seg = ((lane>>3)&1)*16
    uint32_t b_rowbase[4], b_key[4];
    #pragma unroll
    for (int nb = 0; nb < 4; nb++) {
        int nrow = warp_n * 64 + nb * 16 + (lane & 7) + ((lane >> 4) << 3);
        b_rowbase[nb] = (uint32_t)nrow * 128;
        b_key[nb] = (uint32_t)((nrow & 7) << 4);
    }
    uint32_t b_seg = (uint32_t)(((lane >> 3) & 1) * 16);

    float acc[2][8][4];
    #pragma unroll
    for (int mi = 0; mi < 2; mi++)
        #pragma unroll
        for (int ni = 0; ni < 8; ni++)
            #pragma unroll
            for (int j = 0; j < 4; j++) acc[mi][ni][j] = 0.f;

    // ---- prologue ----
    load_stage(0, 0);
    load_stage(1, 1);

    // ---- mainloop ----
    for (int kt = 0; kt < KT; kt++) {
        cp_wait1();
        __syncthreads();
        if (kt + 2 < KT) {
            load_stage((kt + 2) % STAGES, kt + 2);
        } else {
            cp_commit();  // keep group counting consistent
        }

        int s = kt % STAGES;
        uint32_t a_s = stage0 + s * STAGE_BYTES;
        uint32_t b_s = a_s + A_STAGE_BYTES;

        #pragma unroll
        for (int ks = 0; ks < 4; ks++) {
            uint32_t kb = (uint32_t)(ks * 32);
            uint32_t a_frag[2][4];
            #pragma unroll
            for (int mi = 0; mi < 2; mi++) {
                uint32_t addr = a_s + a_rowbase[mi] + ((kb + a_seg) ^ a_key[mi]);
                ldsm_x4(a_frag[mi][0], a_frag[mi][1], a_frag[mi][2], a_frag[mi][3], addr);
            }
            uint32_t b_frag[8][2];
            #pragma unroll
            for (int nb = 0; nb < 4; nb++) {
                uint32_t addr = b_s + b_rowbase[nb] + ((kb + b_seg) ^ b_key[nb]);
                ldsm_x4(b_frag[2 * nb][0], b_frag[2 * nb][1],
                        b_frag[2 * nb + 1][0], b_frag[2 * nb + 1][1], addr);
            }
            #pragma unroll
            for (int mi = 0; mi < 2; mi++)
                #pragma unroll
                for (int ni = 0; ni < 8; ni++)
                    mma16816(acc[mi][ni], a_frag[mi], b_frag[ni]);
        }
        __syncthreads();
    }

    // ---- epilogue: d0/d1 -> (row, col..col+1), d2/d3 -> (row+8, ...) ----
    #pragma unroll
    for (int mi = 0; mi < 2; mi++) {
        int row = m0 + warp_m * 32 + mi * 16 + (lane >> 2);
        #pragma unroll
        for (int ni = 0; ni < 8; ni++) {
            int col = n0 + warp_n * 64 + ni * 8 + (lane & 3) * 2;
            float2 bv = *reinterpret_cast<const float2*>(bias + col);
            float2 v0, v1;
            v0.x = acc[mi][ni][0] + bv.x;
            v0.y = acc[mi][ni][1] + bv.y;
            v1.x = acc[mi][ni][2] + bv.x;
            v1.y = acc[mi][ni][3] + bv.y;
            *reinterpret_cast<float2*>(out + (size_t)row * N_OUT + col) = v0;
            *reinterpret_cast<float2*>(out + (size_t)(row + 8) * N_OUT + col) = v1;
        }
    }
}

// ============================================================================
// kernel_launch
// inputs: x f32 [4096,3072], w_q i32 [12288,96,32], scales f32 [12288,96,1],
//         bias f32 [12288]; output f32 [4096,12288]
// ============================================================================
extern "C" void kernel_launch(void* const* d_in, const int* in_sizes, int n_in,
                              void* d_out, int out_size) {
    const float* x    = (const float*)d_in[0];
    const int*   wq   = (const int*)d_in[1];
    const float* sc   = (const float*)d_in[2];
    const float* bias = (const float*)d_in[3];
    float* out = (float*)d_out;

    cudaFuncSetAttribute(DequantingLinear_gemm_hmma,
                         cudaFuncAttributeMaxDynamicSharedMemorySize, SMEM_SIZE);

    {
        size_t total = (size_t)M_TOK * K_IN / 8;
        DequantingLinear_convert_x<<<(unsigned)((total + 255) / 256), 256>>>(x);
    }
    {
        size_t total = (size_t)N_OUT * K_IN / 8;
        DequantingLinear_dequant_w<<<(unsigned)((total + 255) / 256), 256>>>(wq, sc);
    }
    {
        dim3 grid(N_OUT / BN, M_TOK / BM);  // (96, 32)
        DequantingLinear_gemm_hmma<<<grid, 256, SMEM_SIZE>>>(bias, out);
    }
}